// round 1
// baseline (speedup 1.0000x reference)
#include <cuda_runtime.h>
#include <cuda_bf16.h>
#include <math.h>

// Problem dims (fixed by the dataset)
#define B_ROWS 2048
#define GIN    128
#define GH     128
#define NE     8
#define XDIM   512      // XIN = U = OUT = 512
#define KTOT   (NE * XDIM)   // 4096

// Scratch (allocation-free rule: __device__ globals)
__device__ float g_gate[B_ROWS * NE];
__device__ float g_x1[B_ROWS * XDIM];
__device__ float g_x2[B_ROWS * XDIM];

__device__ __forceinline__ float eluf(float x) {
    return x > 0.0f ? x : expm1f(x);
}

// ---------------------------------------------------------------------------
// Gating: h=ELU(gi@Wg0+bg0); h=ELU(h@Wg1+bg1); g=softmax(h@Wgo+bgo)
// 128 threads per block, 8 rows per block, 256 blocks.
// ---------------------------------------------------------------------------
__global__ __launch_bounds__(128) void gating_kernel(
    const float* __restrict__ GI,
    const float* __restrict__ Wg0, const float* __restrict__ bg0,
    const float* __restrict__ Wg1, const float* __restrict__ bg1,
    const float* __restrict__ Wgo, const float* __restrict__ bgo)
{
    __shared__ float sx[8][GIN];
    __shared__ float sh[8][GH];
    __shared__ float sl[8][NE];

    const int r0  = blockIdx.x * 8;
    const int tid = threadIdx.x;

    for (int idx = tid; idx < 8 * GIN; idx += 128)
        sx[idx >> 7][idx & 127] = GI[(size_t)(r0 + (idx >> 7)) * GIN + (idx & 127)];
    __syncthreads();

    float acc[8];
    // layer 0
    #pragma unroll
    for (int r = 0; r < 8; r++) acc[r] = bg0[tid];
    #pragma unroll 4
    for (int i = 0; i < GIN; i++) {
        float w = Wg0[i * GH + tid];
        #pragma unroll
        for (int r = 0; r < 8; r++) acc[r] += sx[r][i] * w;
    }
    #pragma unroll
    for (int r = 0; r < 8; r++) sh[r][tid] = eluf(acc[r]);
    __syncthreads();

    // layer 1 (writes back into sx)
    #pragma unroll
    for (int r = 0; r < 8; r++) acc[r] = bg1[tid];
    #pragma unroll 4
    for (int i = 0; i < GH; i++) {
        float w = Wg1[i * GH + tid];
        #pragma unroll
        for (int r = 0; r < 8; r++) acc[r] += sh[r][i] * w;
    }
    __syncthreads();
    #pragma unroll
    for (int r = 0; r < 8; r++) sx[r][tid] = eluf(acc[r]);
    __syncthreads();

    // logits: 64 threads, (row, expert)
    if (tid < 64) {
        const int r = tid >> 3, e = tid & 7;
        float a = bgo[e];
        #pragma unroll 4
        for (int i = 0; i < GH; i++) a += sx[r][i] * Wgo[i * NE + e];
        sl[r][e] = a;
    }
    __syncthreads();

    // softmax per row
    if (tid < 8) {
        const int r = tid;
        float mx = sl[r][0];
        #pragma unroll
        for (int e = 1; e < NE; e++) mx = fmaxf(mx, sl[r][e]);
        float ex[NE], s = 0.0f;
        #pragma unroll
        for (int e = 0; e < NE; e++) { ex[e] = expf(sl[r][e] - mx); s += ex[e]; }
        float inv = 1.0f / s;
        #pragma unroll
        for (int e = 0; e < NE; e++)
            g_gate[(size_t)(r0 + r) * NE + e] = ex[e] * inv;
    }
}

// ---------------------------------------------------------------------------
// Expert layer as a single fused GEMM:
//   Y[b,u] = act( sum_{e,i} g[b,e]*X[b,i]*alpha[e,u,i] + sum_e g[b,e]*beta[e,u] )
// M=2048, N=512, K=4096.  g-scaling applied on A-tile load (k-tiles never
// cross expert boundaries since 512 % BK == 0).
// BM=128, BN=64, BK=16, 256 threads, 8x4 thread tile, double-buffered smem.
// ---------------------------------------------------------------------------
#define BM 128
#define BN 64
#define BK 16
#define NK (KTOT / BK)   // 256

__global__ __launch_bounds__(256, 1) void expert_kernel(
    const float* __restrict__ Xext,
    const float* __restrict__ alpha,   // (8, 512, 512), [e][u][i]
    const float* __restrict__ beta,    // (8, 512)
    float* __restrict__ Yext,
    int xsel,      // 0 = Xext, 1 = g_x1, 2 = g_x2
    int ysel,      // 0 = Yext, 1 = g_x1, 2 = g_x2
    int apply_elu)
{
    const float* X = (xsel == 0) ? Xext : (xsel == 1 ? g_x1 : g_x2);
    float*       Y = (ysel == 0) ? Yext : (ysel == 1 ? g_x1 : g_x2);

    __shared__ float As[2][BK][BM];
    __shared__ float Bs[2][BK][BN];
    __shared__ float sg[BM][NE];
    __shared__ float sbeta[NE][BN];

    const int tid = threadIdx.x;
    const int m0  = blockIdx.y * BM;
    const int n0  = blockIdx.x * BN;

    for (int idx = tid; idx < BM * NE; idx += 256)
        sg[idx >> 3][idx & 7] = g_gate[(size_t)(m0 + (idx >> 3)) * NE + (idx & 7)];
    for (int idx = tid; idx < NE * BN; idx += 256)
        sbeta[idx / BN][idx % BN] = beta[(idx / BN) * XDIM + n0 + (idx % BN)];
    __syncthreads();

    // loader coordinates
    const int lrow = tid >> 2;           // 0..63
    const int lc4  = (tid & 3) * 4;      // 0,4,8,12

    // compute coordinates: 16 (n) x 16 (m) thread grid
    const int tx = tid & 15;             // 4 cols each -> 64
    const int ty = tid >> 4;             // 8 rows each -> 128

    float4 la0, la1, lb;

    auto load_tile = [&](int kt) {
        const int kg = kt * BK;
        const int e  = kg >> 9;          // kg / 512
        const int ii = kg & 511;
        la0 = *(const float4*)(X + (size_t)(m0 + lrow) * XDIM + ii + lc4);
        la1 = *(const float4*)(X + (size_t)(m0 + 64 + lrow) * XDIM + ii + lc4);
        const float s0 = sg[lrow][e];
        const float s1 = sg[64 + lrow][e];
        la0.x *= s0; la0.y *= s0; la0.z *= s0; la0.w *= s0;
        la1.x *= s1; la1.y *= s1; la1.z *= s1; la1.w *= s1;
        lb = *(const float4*)(alpha + ((size_t)e * XDIM + (n0 + lrow)) * XDIM + ii + lc4);
    };
    auto store_tile = [&](int buf) {
        As[buf][lc4 + 0][lrow] = la0.x;
        As[buf][lc4 + 1][lrow] = la0.y;
        As[buf][lc4 + 2][lrow] = la0.z;
        As[buf][lc4 + 3][lrow] = la0.w;
        As[buf][lc4 + 0][64 + lrow] = la1.x;
        As[buf][lc4 + 1][64 + lrow] = la1.y;
        As[buf][lc4 + 2][64 + lrow] = la1.z;
        As[buf][lc4 + 3][64 + lrow] = la1.w;
        Bs[buf][lc4 + 0][lrow] = lb.x;
        Bs[buf][lc4 + 1][lrow] = lb.y;
        Bs[buf][lc4 + 2][lrow] = lb.z;
        Bs[buf][lc4 + 3][lrow] = lb.w;
    };

    float acc[8][4];
    #pragma unroll
    for (int i = 0; i < 8; i++)
        #pragma unroll
        for (int j = 0; j < 4; j++) acc[i][j] = 0.0f;

    load_tile(0);
    store_tile(0);
    __syncthreads();

    int cur = 0;
    for (int kt = 0; kt < NK; kt++) {
        if (kt + 1 < NK) load_tile(kt + 1);

        #pragma unroll
        for (int k = 0; k < BK; k++) {
            float4 a0 = *(const float4*)&As[cur][k][ty * 8];
            float4 a1 = *(const float4*)&As[cur][k][ty * 8 + 4];
            float4 b  = *(const float4*)&Bs[cur][k][tx * 4];
            const float av[8] = {a0.x, a0.y, a0.z, a0.w, a1.x, a1.y, a1.z, a1.w};
            const float bv[4] = {b.x, b.y, b.z, b.w};
            #pragma unroll
            for (int mi = 0; mi < 8; mi++)
                #pragma unroll
                for (int ni = 0; ni < 4; ni++)
                    acc[mi][ni] += av[mi] * bv[ni];
        }

        if (kt + 1 < NK) store_tile(cur ^ 1);
        __syncthreads();
        cur ^= 1;
    }

    // epilogue: bias (g @ beta) + optional ELU, vectorized stores
    #pragma unroll
    for (int mi = 0; mi < 8; mi++) {
        const int row = ty * 8 + mi;
        float4 o;
        float* op = &o.x;
        #pragma unroll
        for (int ni = 0; ni < 4; ni++) {
            float bias = 0.0f;
            #pragma unroll
            for (int e = 0; e < NE; e++)
                bias += sg[row][e] * sbeta[e][tx * 4 + ni];
            float v = acc[mi][ni] + bias;
            op[ni] = apply_elu ? eluf(v) : v;
        }
        *(float4*)(Y + (size_t)(m0 + row) * XDIM + n0 + tx * 4) = o;
    }
}

// ---------------------------------------------------------------------------
// Launch: gating, then three expert-layer GEMMs (graph-capturable, no allocs)
// ---------------------------------------------------------------------------
extern "C" void kernel_launch(void* const* d_in, const int* in_sizes, int n_in,
                              void* d_out, int out_size) {
    const float* gi  = (const float*)d_in[0];
    const float* xin = (const float*)d_in[1];
    const float* Wg0 = (const float*)d_in[2];
    const float* bg0 = (const float*)d_in[3];
    const float* Wg1 = (const float*)d_in[4];
    const float* bg1 = (const float*)d_in[5];
    const float* Wgo = (const float*)d_in[6];
    const float* bgo = (const float*)d_in[7];
    const float* a0  = (const float*)d_in[8];
    const float* be0 = (const float*)d_in[9];
    const float* a1  = (const float*)d_in[10];
    const float* be1 = (const float*)d_in[11];
    const float* a2  = (const float*)d_in[12];
    const float* be2 = (const float*)d_in[13];
    float* out = (float*)d_out;

    gating_kernel<<<B_ROWS / 8, 128>>>(gi, Wg0, bg0, Wg1, bg1, Wgo, bgo);

    dim3 grid(XDIM / BN, B_ROWS / BM);   // (8, 16)
    // layer 0: X = expert_input, Y = g_x1, ELU
    expert_kernel<<<grid, 256>>>(xin, a0, be0, nullptr, 0, 1, 1);
    // layer 1: X = g_x1, Y = g_x2, ELU
    expert_kernel<<<grid, 256>>>(nullptr, a1, be1, nullptr, 1, 2, 1);
    // layer 2: X = g_x2, Y = d_out, no activation
    expert_kernel<<<grid, 256>>>(nullptr, a2, be2, out, 2, 0, 0);
}

// round 3
// speedup vs baseline: 2.8178x; 2.8178x over previous
#include <cuda_runtime.h>
#include <cuda_bf16.h>
#include <math.h>
#include <stdint.h>

// Problem dims (fixed by the dataset)
#define B_ROWS 2048
#define GIN    128
#define GH     128
#define NE     8
#define XDIM   512
#define KTOT   (NE * XDIM)   // 4096

// Static scratch (allocation-free rule)
__device__ __align__(16) float g_gate[B_ROWS * NE];
__device__ __align__(16) float g_x1[B_ROWS * XDIM];
__device__ __align__(16) float g_x2[B_ROWS * XDIM];

__device__ __forceinline__ float eluf(float x) { return x > 0.0f ? x : expm1f(x); }
__device__ __forceinline__ uint32_t tf32u(float x) {
    uint32_t r; asm("cvt.rna.tf32.f32 %0, %1;" : "=r"(r) : "f"(x)); return r;
}

// ---------------------------------------------------------------------------
// Gating network (unchanged, passed in R1)
// ---------------------------------------------------------------------------
__global__ __launch_bounds__(128) void gating_kernel(
    const float* __restrict__ GI,
    const float* __restrict__ Wg0, const float* __restrict__ bg0,
    const float* __restrict__ Wg1, const float* __restrict__ bg1,
    const float* __restrict__ Wgo, const float* __restrict__ bgo)
{
    __shared__ float sx[8][GIN];
    __shared__ float sh[8][GH];
    __shared__ float sl[8][NE];

    const int r0  = blockIdx.x * 8;
    const int tid = threadIdx.x;

    for (int idx = tid; idx < 8 * GIN; idx += 128)
        sx[idx >> 7][idx & 127] = GI[(size_t)(r0 + (idx >> 7)) * GIN + (idx & 127)];
    __syncthreads();

    float acc[8];
    #pragma unroll
    for (int r = 0; r < 8; r++) acc[r] = bg0[tid];
    #pragma unroll 4
    for (int i = 0; i < GIN; i++) {
        float w = Wg0[i * GH + tid];
        #pragma unroll
        for (int r = 0; r < 8; r++) acc[r] += sx[r][i] * w;
    }
    #pragma unroll
    for (int r = 0; r < 8; r++) sh[r][tid] = eluf(acc[r]);
    __syncthreads();

    #pragma unroll
    for (int r = 0; r < 8; r++) acc[r] = bg1[tid];
    #pragma unroll 4
    for (int i = 0; i < GH; i++) {
        float w = Wg1[i * GH + tid];
        #pragma unroll
        for (int r = 0; r < 8; r++) acc[r] += sh[r][i] * w;
    }
    __syncthreads();
    #pragma unroll
    for (int r = 0; r < 8; r++) sx[r][tid] = eluf(acc[r]);
    __syncthreads();

    if (tid < 64) {
        const int r = tid >> 3, e = tid & 7;
        float a = bgo[e];
        #pragma unroll 4
        for (int i = 0; i < GH; i++) a += sx[r][i] * Wgo[i * NE + e];
        sl[r][e] = a;
    }
    __syncthreads();

    if (tid < 8) {
        const int r = tid;
        float mx = sl[r][0];
        #pragma unroll
        for (int e = 1; e < NE; e++) mx = fmaxf(mx, sl[r][e]);
        float ex[NE], s = 0.0f;
        #pragma unroll
        for (int e = 0; e < NE; e++) { ex[e] = expf(sl[r][e] - mx); s += ex[e]; }
        float inv = 1.0f / s;
        #pragma unroll
        for (int e = 0; e < NE; e++)
            g_gate[(size_t)(r0 + r) * NE + e] = ex[e] * inv;
    }
}

// ---------------------------------------------------------------------------
// Expert layer GEMM via mma.sync tf32 (sm_80+ path; tcgen05 unavailable at
// the harness's ptxas target).
//   D[2048,512] = A'[2048,4096] @ B[4096,512]
//   A'[b, e*512+i] = g[b,e]*X[b,i]  (scale folded into fragment load)
//   B [e*512+i, n] = alpha[e][n][i] (already K-major per (e,n) row)
// Tile 128x64 per CTA (grid 8x16=128), 4 warps, warptile 64x32,
// BK=32, 4-stage cp.async pipeline, smem rows padded to 36 floats.
// ---------------------------------------------------------------------------
#define BM 128
#define BN 64
#define BK 32
#define NKCH (KTOT / BK)    // 128
#define NST 4
#define ASTRIDE 36
#define A_STG_F (BM * ASTRIDE)            // 4608 floats
#define B_STG_F (BN * ASTRIDE)            // 2304 floats
#define STG_F   (A_STG_F + B_STG_F)       // 6912 floats
#define SMEM_FLOATS (NST * STG_F + BM * NE + NE * BN)
#define SMEM_BYTES  (SMEM_FLOATS * 4)     // 116736 B

__device__ __forceinline__ void cp16(uint32_t dst, const float* src) {
    asm volatile("cp.async.cg.shared.global [%0], [%1], 16;"
                 :: "r"(dst), "l"(__cvta_generic_to_global(src)) : "memory");
}
__device__ __forceinline__ void mma8(float* c, const uint32_t* a, const uint32_t* b) {
    asm volatile(
        "mma.sync.aligned.m16n8k8.row.col.f32.tf32.tf32.f32 "
        "{%0,%1,%2,%3}, {%4,%5,%6,%7}, {%8,%9}, {%0,%1,%2,%3};"
        : "+f"(c[0]), "+f"(c[1]), "+f"(c[2]), "+f"(c[3])
        : "r"(a[0]), "r"(a[1]), "r"(a[2]), "r"(a[3]), "r"(b[0]), "r"(b[1]));
}

__global__ __launch_bounds__(128, 1) void gemm_kernel(
    const float* __restrict__ Xext,
    const float* __restrict__ alpha,   // (8, 512, 512) [e][u][i]
    const float* __restrict__ beta,    // (8, 512)
    float* __restrict__ Yext,
    int xsel, int ysel, int apply_elu)
{
    extern __shared__ float smem[];
    const float* X = (xsel == 0) ? Xext : (xsel == 1 ? g_x1 : g_x2);
    float*       Y = (ysel == 0) ? Yext : (ysel == 1 ? g_x1 : g_x2);

    float* sg    = smem + NST * STG_F;       // [128][8]
    float* sbeta = sg + BM * NE;             // [8][64]

    const int tid  = threadIdx.x;
    const int wid  = tid >> 5, lane = tid & 31;
    const int qid  = lane >> 2, qk = lane & 3;
    const int wm   = (wid & 1) * 64;         // warp m offset in tile
    const int wn   = (wid >> 1) * 32;        // warp n offset in tile
    const int n0   = blockIdx.x * BN;
    const int m0   = blockIdx.y * BM;

    const uint32_t smem_u = (uint32_t)__cvta_generic_to_shared(smem);

    auto load_chunk = [&](int s, int kt) {
        const int e  = kt >> 4;
        const int i0 = (kt & 15) * 32;
        const float* Ab = X + (size_t)m0 * XDIM + i0;
        const float* Bb = alpha + ((size_t)e * XDIM + n0) * XDIM + i0;
        const uint32_t sa  = smem_u + s * (STG_F * 4);
        const uint32_t sbm = sa + A_STG_F * 4;
        #pragma unroll
        for (int i = 0; i < 8; i++) {            // A: 128 rows x 128B
            int unit = i * 128 + tid;
            int row = unit >> 3, c16 = unit & 7;
            cp16(sa + row * (ASTRIDE * 4) + c16 * 16,
                 Ab + (size_t)row * XDIM + c16 * 4);
        }
        #pragma unroll
        for (int i = 0; i < 4; i++) {            // B: 64 rows x 128B
            int unit = i * 128 + tid;
            int row = unit >> 3, c16 = unit & 7;
            cp16(sbm + row * (ASTRIDE * 4) + c16 * 16,
                 Bb + (size_t)row * XDIM + c16 * 4);
        }
    };

    // prefetch NST-1 stages
    #pragma unroll
    for (int s = 0; s < NST - 1; s++) {
        load_chunk(s, s);
        asm volatile("cp.async.commit_group;" ::: "memory");
    }

    // gate / beta tiles into smem (overlaps with in-flight cp.async)
    for (int i = tid; i < BM * NE; i += 128)
        sg[i] = g_gate[(size_t)m0 * NE + i];
    for (int i = tid; i < NE * BN; i += 128)
        sbeta[i] = beta[(size_t)(i >> 6) * XDIM + n0 + (i & 63)];

    float c[4][4][4];
    #pragma unroll
    for (int mt = 0; mt < 4; mt++)
        #pragma unroll
        for (int nt = 0; nt < 4; nt++)
            #pragma unroll
            for (int j = 0; j < 4; j++) c[mt][nt][j] = 0.0f;

    float ga[4][2];

    for (int kt = 0; kt < NKCH; kt++) {
        asm volatile("cp.async.wait_group 2;" ::: "memory");
        __syncthreads();

        if (kt + NST - 1 < NKCH) load_chunk((kt + NST - 1) & (NST - 1), kt + NST - 1);
        asm volatile("cp.async.commit_group;" ::: "memory");

        if ((kt & 15) == 0) {
            const int e = kt >> 4;
            #pragma unroll
            for (int mt = 0; mt < 4; mt++) {
                ga[mt][0] = sg[(wm + mt * 16 + qid) * NE + e];
                ga[mt][1] = sg[(wm + mt * 16 + qid + 8) * NE + e];
            }
        }

        const float* As = smem + (kt & (NST - 1)) * STG_F;
        const float* Bs = As + A_STG_F;

        #pragma unroll
        for (int ks = 0; ks < 4; ks++) {
            const int k = ks * 8 + qk;
            uint32_t a[4][4], b[4][2];
            #pragma unroll
            for (int mt = 0; mt < 4; mt++) {
                const float* ap = As + (wm + mt * 16 + qid) * ASTRIDE + k;
                a[mt][0] = tf32u(ga[mt][0] * ap[0]);
                a[mt][2] = tf32u(ga[mt][0] * ap[4]);
                a[mt][1] = tf32u(ga[mt][1] * ap[8 * ASTRIDE]);
                a[mt][3] = tf32u(ga[mt][1] * ap[8 * ASTRIDE + 4]);
            }
            #pragma unroll
            for (int nt = 0; nt < 4; nt++) {
                const float* bp = Bs + (wn + nt * 8 + qid) * ASTRIDE + k;
                b[nt][0] = tf32u(bp[0]);
                b[nt][1] = tf32u(bp[4]);
            }
            #pragma unroll
            for (int mt = 0; mt < 4; mt++)
                #pragma unroll
                for (int nt = 0; nt < 4; nt++)
                    mma8(c[mt][nt], a[mt], b[nt]);
        }
    }

    // Epilogue: bias (g @ beta) + optional ELU
    #pragma unroll
    for (int mt = 0; mt < 4; mt++) {
        const int r0 = wm + mt * 16 + qid;
        const int r1 = r0 + 8;
        float g0[NE], g1[NE];
        #pragma unroll
        for (int e = 0; e < NE; e++) { g0[e] = sg[r0 * NE + e]; g1[e] = sg[r1 * NE + e]; }
        #pragma unroll
        for (int nt = 0; nt < 4; nt++) {
            const int cc = wn + nt * 8 + 2 * qk;
            float b00 = 0.f, b01 = 0.f, b10 = 0.f, b11 = 0.f;
            #pragma unroll
            for (int e = 0; e < NE; e++) {
                const float s0 = sbeta[e * BN + cc], s1 = sbeta[e * BN + cc + 1];
                b00 += g0[e] * s0; b01 += g0[e] * s1;
                b10 += g1[e] * s0; b11 += g1[e] * s1;
            }
            float v00 = c[mt][nt][0] + b00, v01 = c[mt][nt][1] + b01;
            float v10 = c[mt][nt][2] + b10, v11 = c[mt][nt][3] + b11;
            if (apply_elu) {
                v00 = eluf(v00); v01 = eluf(v01);
                v10 = eluf(v10); v11 = eluf(v11);
            }
            float2 o0 = {v00, v01}, o1 = {v10, v11};
            *(float2*)(Y + (size_t)(m0 + r0) * XDIM + n0 + cc) = o0;
            *(float2*)(Y + (size_t)(m0 + r1) * XDIM + n0 + cc) = o1;
        }
    }
}

// ---------------------------------------------------------------------------
// Launch (graph-capturable)
// ---------------------------------------------------------------------------
extern "C" void kernel_launch(void* const* d_in, const int* in_sizes, int n_in,
                              void* d_out, int out_size) {
    const float* gi  = (const float*)d_in[0];
    const float* xin = (const float*)d_in[1];
    const float* Wg0 = (const float*)d_in[2];
    const float* bg0 = (const float*)d_in[3];
    const float* Wg1 = (const float*)d_in[4];
    const float* bg1 = (const float*)d_in[5];
    const float* Wgo = (const float*)d_in[6];
    const float* bgo = (const float*)d_in[7];
    const float* a0  = (const float*)d_in[8];
    const float* be0 = (const float*)d_in[9];
    const float* a1  = (const float*)d_in[10];
    const float* be1 = (const float*)d_in[11];
    const float* a2  = (const float*)d_in[12];
    const float* be2 = (const float*)d_in[13];
    float* out = (float*)d_out;

    static int smem_set = 0;
    if (!smem_set) {
        cudaFuncSetAttribute(gemm_kernel, cudaFuncAttributeMaxDynamicSharedMemorySize, SMEM_BYTES);
        smem_set = 1;
    }

    gating_kernel<<<B_ROWS / 8, 128>>>(gi, Wg0, bg0, Wg1, bg1, Wgo, bgo);

    dim3 grid(XDIM / BN, B_ROWS / BM);   // (8, 16) = 128 CTAs
    gemm_kernel<<<grid, 128, SMEM_BYTES>>>(xin,     a0, be0, nullptr, 0, 1, 1); // -> g_x1
    gemm_kernel<<<grid, 128, SMEM_BYTES>>>(nullptr, a1, be1, nullptr, 1, 2, 1); // -> g_x2
    gemm_kernel<<<grid, 128, SMEM_BYTES>>>(nullptr, a2, be2, out,     2, 0, 0); // -> d_out
}

// round 4
// speedup vs baseline: 3.8975x; 1.3832x over previous
#include <cuda_runtime.h>
#include <cuda_bf16.h>
#include <math.h>
#include <stdint.h>

#define B_ROWS 2048
#define GIN    128
#define GH     128
#define NE     8
#define XDIM   512

// Static scratch (allocation-free rule)
__device__ __align__(16) float g_gate[B_ROWS * NE];
__device__ __align__(16) float g_xt[(size_t)B_ROWS * XDIM];            // tf32-rounded activations
__device__ __align__(16) float g_alpha[(size_t)NE * XDIM * XDIM];      // tf32-rounded weights
__device__ __align__(16) float g_part[4ull * B_ROWS * XDIM];           // ksplit partials (16 MB)

__device__ __forceinline__ float eluf(float x) { return x > 0.0f ? x : expm1f(x); }
__device__ __forceinline__ float tf32r(float x) {
    float r; asm("cvt.rna.tf32.f32 %0, %1;" : "=f"(r) : "f"(x)); return r;
}

// ---------------------------------------------------------------------------
// Gating network (validated in R1/R3)
// ---------------------------------------------------------------------------
__global__ __launch_bounds__(128) void gating_kernel(
    const float* __restrict__ GI,
    const float* __restrict__ Wg0, const float* __restrict__ bg0,
    const float* __restrict__ Wg1, const float* __restrict__ bg1,
    const float* __restrict__ Wgo, const float* __restrict__ bgo)
{
    __shared__ float sx[8][GIN];
    __shared__ float sh[8][GH];
    __shared__ float sl[8][NE];

    const int r0  = blockIdx.x * 8;
    const int tid = threadIdx.x;

    for (int idx = tid; idx < 8 * GIN; idx += 128)
        sx[idx >> 7][idx & 127] = GI[(size_t)(r0 + (idx >> 7)) * GIN + (idx & 127)];
    __syncthreads();

    float acc[8];
    #pragma unroll
    for (int r = 0; r < 8; r++) acc[r] = bg0[tid];
    #pragma unroll 4
    for (int i = 0; i < GIN; i++) {
        float w = Wg0[i * GH + tid];
        #pragma unroll
        for (int r = 0; r < 8; r++) acc[r] += sx[r][i] * w;
    }
    #pragma unroll
    for (int r = 0; r < 8; r++) sh[r][tid] = eluf(acc[r]);
    __syncthreads();

    #pragma unroll
    for (int r = 0; r < 8; r++) acc[r] = bg1[tid];
    #pragma unroll 4
    for (int i = 0; i < GH; i++) {
        float w = Wg1[i * GH + tid];
        #pragma unroll
        for (int r = 0; r < 8; r++) acc[r] += sh[r][i] * w;
    }
    __syncthreads();
    #pragma unroll
    for (int r = 0; r < 8; r++) sx[r][tid] = eluf(acc[r]);
    __syncthreads();

    if (tid < 64) {
        const int r = tid >> 3, e = tid & 7;
        float a = bgo[e];
        #pragma unroll 4
        for (int i = 0; i < GH; i++) a += sx[r][i] * Wgo[i * NE + e];
        sl[r][e] = a;
    }
    __syncthreads();

    if (tid < 8) {
        const int r = tid;
        float mx = sl[r][0];
        #pragma unroll
        for (int e = 1; e < NE; e++) mx = fmaxf(mx, sl[r][e]);
        float ex[NE], s = 0.0f;
        #pragma unroll
        for (int e = 0; e < NE; e++) { ex[e] = expf(sl[r][e] - mx); s += ex[e]; }
        float inv = 1.0f / s;
        #pragma unroll
        for (int e = 0; e < NE; e++)
            g_gate[(size_t)(r0 + r) * NE + e] = ex[e] * inv;
    }
}

// tf32-round a buffer (float4 grid-stride)
__global__ __launch_bounds__(256) void cvt_round_kernel(
    const float* __restrict__ src, float* __restrict__ dst, int n4)
{
    for (int i = blockIdx.x * 256 + threadIdx.x; i < n4; i += gridDim.x * 256) {
        float4 v = ((const float4*)src)[i];
        v.x = tf32r(v.x); v.y = tf32r(v.y); v.z = tf32r(v.z); v.w = tf32r(v.w);
        ((float4*)dst)[i] = v;
    }
}

// ---------------------------------------------------------------------------
// GEMM: per (n-block, m-block, ksplit) CTA computes over 2 experts:
//   part[z][b,n] = g_e1*( (g_e0/g_e1)*P_e0 + P_e1 ) + g_e0*beta_e0 + g_e1*beta_e1
// Tile 128x128, 4 warps, warptile 64x64, BK=32, NST=2 cp.async.
// Operands in smem are pre-rounded tf32 -> inner loop = LDS + MMA only.
// ---------------------------------------------------------------------------
#define BM 128
#define BN 128
#define BK 32
#define NKT 32                       // 2 experts * 512 / 32
#define PAD 36
#define STG_F (BM * PAD + BN * PAD)  // 9216 floats per stage
#define NST 2
#define SMEM_FLOATS (NST * STG_F + BM * 2 + 2 * BN)
#define SMEM_BYTES  (SMEM_FLOATS * 4)   // 75776

__device__ __forceinline__ void cp16(uint32_t dst, const float* src) {
    asm volatile("cp.async.cg.shared.global [%0], [%1], 16;"
                 :: "r"(dst), "l"(__cvta_generic_to_global(src)) : "memory");
}
__device__ __forceinline__ void mma8(float* c, const uint32_t* a, const uint32_t* b) {
    asm volatile(
        "mma.sync.aligned.m16n8k8.row.col.f32.tf32.tf32.f32 "
        "{%0,%1,%2,%3}, {%4,%5,%6,%7}, {%8,%9}, {%0,%1,%2,%3};"
        : "+f"(c[0]), "+f"(c[1]), "+f"(c[2]), "+f"(c[3])
        : "r"(a[0]), "r"(a[1]), "r"(a[2]), "r"(a[3]), "r"(b[0]), "r"(b[1]));
}

__global__ __launch_bounds__(128) void gemm_kernel(const float* __restrict__ beta)
{
    extern __shared__ float smem[];
    float* sg    = smem + NST * STG_F;   // [128][2] gates for expert pair
    float* sbeta = sg + BM * 2;          // [2][128]

    const int tid  = threadIdx.x;
    const int wid  = tid >> 5, lane = tid & 31;
    const int qid  = lane >> 2, qk = lane & 3;
    const int wm   = (wid & 1) * 64;
    const int wn   = (wid >> 1) * 64;
    const int n0   = blockIdx.x * BN;
    const int m0   = blockIdx.y * BM;
    const int e0   = blockIdx.z * 2;

    const uint32_t smem_u = (uint32_t)__cvta_generic_to_shared(smem);

    auto load_chunk = [&](int s, int c) {
        const int el = c >> 4;                 // 0/1 within pair
        const int i0 = (c & 15) * 32;
        const float* Ab = g_xt + (size_t)m0 * XDIM + i0;
        const float* Bb = g_alpha + ((size_t)(e0 + el) * XDIM + n0) * XDIM + i0;
        const uint32_t sa  = smem_u + s * (STG_F * 4);
        const uint32_t sbm = sa + BM * PAD * 4;
        #pragma unroll
        for (int i = 0; i < 8; i++) {          // A: 128 rows x 8 x16B
            int unit = i * 128 + tid;
            int row = unit >> 3, c16 = unit & 7;
            cp16(sa + row * (PAD * 4) + c16 * 16, Ab + (size_t)row * XDIM + c16 * 4);
        }
        #pragma unroll
        for (int i = 0; i < 8; i++) {          // B: 128 rows x 8 x16B
            int unit = i * 128 + tid;
            int row = unit >> 3, c16 = unit & 7;
            cp16(sbm + row * (PAD * 4) + c16 * 16, Bb + (size_t)row * XDIM + c16 * 4);
        }
    };

    load_chunk(0, 0);
    asm volatile("cp.async.commit_group;" ::: "memory");
    load_chunk(1, 1);
    asm volatile("cp.async.commit_group;" ::: "memory");

    // gates + betas (overlap with cp.async)
    sg[tid * 2 + 0] = g_gate[(size_t)(m0 + tid) * NE + e0];
    sg[tid * 2 + 1] = g_gate[(size_t)(m0 + tid) * NE + e0 + 1];
    sbeta[tid]       = beta[(size_t)e0 * XDIM + n0 + tid];
    sbeta[128 + tid] = beta[(size_t)(e0 + 1) * XDIM + n0 + tid];

    float c[4][8][4];
    #pragma unroll
    for (int mt = 0; mt < 4; mt++)
        #pragma unroll
        for (int nt = 0; nt < 8; nt++)
            #pragma unroll
            for (int j = 0; j < 4; j++) c[mt][nt][j] = 0.0f;

    for (int kt = 0; kt < NKT; kt++) {
        asm volatile("cp.async.wait_group 1;" ::: "memory");
        __syncthreads();

        const uint32_t* As = (const uint32_t*)(smem + (kt & 1) * STG_F);
        const uint32_t* Bs = As + BM * PAD;

        #pragma unroll
        for (int ks = 0; ks < 4; ks++) {
            const int k = ks * 8 + qk;
            uint32_t a[4][4], b[8][2];
            #pragma unroll
            for (int mt = 0; mt < 4; mt++) {
                const uint32_t* ap = As + (wm + mt * 16 + qid) * PAD + k;
                a[mt][0] = ap[0];
                a[mt][1] = ap[8 * PAD];
                a[mt][2] = ap[4];
                a[mt][3] = ap[8 * PAD + 4];
            }
            #pragma unroll
            for (int nt = 0; nt < 8; nt++) {
                const uint32_t* bp = Bs + (wn + nt * 8 + qid) * PAD + k;
                b[nt][0] = bp[0];
                b[nt][1] = bp[4];
            }
            #pragma unroll
            for (int mt = 0; mt < 4; mt++)
                #pragma unroll
                for (int nt = 0; nt < 8; nt++)
                    mma8(c[mt][nt], a[mt], b[nt]);
        }

        if (kt == 15) {   // expert boundary: c *= g_e0/g_e1 (exact fold, single acc set)
            #pragma unroll
            for (int mt = 0; mt < 4; mt++) {
                const int r0 = wm + mt * 16 + qid, r1 = r0 + 8;
                const float t0 = sg[r0 * 2] / sg[r0 * 2 + 1];
                const float t1 = sg[r1 * 2] / sg[r1 * 2 + 1];
                #pragma unroll
                for (int nt = 0; nt < 8; nt++) {
                    c[mt][nt][0] *= t0; c[mt][nt][1] *= t0;
                    c[mt][nt][2] *= t1; c[mt][nt][3] *= t1;
                }
            }
        }

        __syncthreads();
        if (kt + 2 < NKT) load_chunk(kt & 1, kt + 2);
        asm volatile("cp.async.commit_group;" ::: "memory");
    }

    // epilogue -> partial buffer
    float* P = g_part + (size_t)blockIdx.z * B_ROWS * XDIM;
    #pragma unroll
    for (int mt = 0; mt < 4; mt++) {
        const int r0 = wm + mt * 16 + qid, r1 = r0 + 8;
        const float ga0 = sg[r0 * 2], gb0 = sg[r0 * 2 + 1];
        const float ga1 = sg[r1 * 2], gb1 = sg[r1 * 2 + 1];
        #pragma unroll
        for (int nt = 0; nt < 8; nt++) {
            const int cc = wn + nt * 8 + 2 * qk;
            const float be00 = sbeta[cc], be01 = sbeta[cc + 1];
            const float be10 = sbeta[128 + cc], be11 = sbeta[128 + cc + 1];
            float2 o0, o1;
            o0.x = gb0 * c[mt][nt][0] + ga0 * be00 + gb0 * be10;
            o0.y = gb0 * c[mt][nt][1] + ga0 * be01 + gb0 * be11;
            o1.x = gb1 * c[mt][nt][2] + ga1 * be00 + gb1 * be10;
            o1.y = gb1 * c[mt][nt][3] + ga1 * be01 + gb1 * be11;
            *(float2*)(P + (size_t)(m0 + r0) * XDIM + n0 + cc) = o0;
            *(float2*)(P + (size_t)(m0 + r1) * XDIM + n0 + cc) = o1;
        }
    }
}

// Sum 4 partials; mode 1: ELU + tf32-round -> g_xt; mode 0: raw -> dst
__global__ __launch_bounds__(256) void reduce_kernel(float* __restrict__ dst, int mode)
{
    const int n4 = B_ROWS * XDIM / 4;
    const float4* p0 = (const float4*)g_part;
    const float4* p1 = (const float4*)(g_part + (size_t)1 * B_ROWS * XDIM);
    const float4* p2 = (const float4*)(g_part + (size_t)2 * B_ROWS * XDIM);
    const float4* p3 = (const float4*)(g_part + (size_t)3 * B_ROWS * XDIM);
    float4* out = (mode == 1) ? (float4*)g_xt : (float4*)dst;
    for (int i = blockIdx.x * 256 + threadIdx.x; i < n4; i += gridDim.x * 256) {
        float4 a = p0[i], b = p1[i], c2 = p2[i], d = p3[i];
        float4 v;
        v.x = a.x + b.x + c2.x + d.x;
        v.y = a.y + b.y + c2.y + d.y;
        v.z = a.z + b.z + c2.z + d.z;
        v.w = a.w + b.w + c2.w + d.w;
        if (mode == 1) {
            v.x = tf32r(eluf(v.x)); v.y = tf32r(eluf(v.y));
            v.z = tf32r(eluf(v.z)); v.w = tf32r(eluf(v.w));
        }
        out[i] = v;
    }
}

// ---------------------------------------------------------------------------
extern "C" void kernel_launch(void* const* d_in, const int* in_sizes, int n_in,
                              void* d_out, int out_size) {
    const float* gi  = (const float*)d_in[0];
    const float* xin = (const float*)d_in[1];
    const float* Wg0 = (const float*)d_in[2];
    const float* bg0 = (const float*)d_in[3];
    const float* Wg1 = (const float*)d_in[4];
    const float* bg1 = (const float*)d_in[5];
    const float* Wgo = (const float*)d_in[6];
    const float* bgo = (const float*)d_in[7];
    const float* a0  = (const float*)d_in[8];
    const float* be0 = (const float*)d_in[9];
    const float* a1  = (const float*)d_in[10];
    const float* be1 = (const float*)d_in[11];
    const float* a2  = (const float*)d_in[12];
    const float* be2 = (const float*)d_in[13];
    float* out = (float*)d_out;

    static int init_done = 0;
    if (!init_done) {
        cudaFuncSetAttribute(gemm_kernel, cudaFuncAttributeMaxDynamicSharedMemorySize, SMEM_BYTES);
        init_done = 1;
    }

    float* d_xt; cudaGetSymbolAddress((void**)&d_xt, g_xt);
    float* d_al; cudaGetSymbolAddress((void**)&d_al, g_alpha);

    gating_kernel<<<B_ROWS / 8, 128>>>(gi, Wg0, bg0, Wg1, bg1, Wgo, bgo);
    cvt_round_kernel<<<256, 256>>>(xin, d_xt, B_ROWS * XDIM / 4);

    dim3 grid(XDIM / BN, B_ROWS / BM, 4);   // (4, 16, 4) = 256 CTAs

    // layer 0
    cvt_round_kernel<<<512, 256>>>(a0, d_al, NE * XDIM * XDIM / 4);
    gemm_kernel<<<grid, 128, SMEM_BYTES>>>(be0);
    reduce_kernel<<<512, 256>>>(nullptr, 1);
    // layer 1
    cvt_round_kernel<<<512, 256>>>(a1, d_al, NE * XDIM * XDIM / 4);
    gemm_kernel<<<grid, 128, SMEM_BYTES>>>(be1);
    reduce_kernel<<<512, 256>>>(nullptr, 1);
    // layer 2
    cvt_round_kernel<<<512, 256>>>(a2, d_al, NE * XDIM * XDIM / 4);
    gemm_kernel<<<grid, 128, SMEM_BYTES>>>(be2);
    reduce_kernel<<<512, 256>>>(out, 0);
}

// round 5
// speedup vs baseline: 4.2345x; 1.0865x over previous
#include <cuda_runtime.h>
#include <cuda_bf16.h>
#include <math.h>
#include <stdint.h>

#define B_ROWS 2048
#define GIN    128
#define GH     128
#define NE     8
#define XDIM   512

// Static scratch (allocation-free rule)
__device__ __align__(16) float g_gate[B_ROWS * NE];
__device__ __align__(16) float g_xt[(size_t)B_ROWS * XDIM];            // tf32-rounded activations
__device__ __align__(16) float g_alpha[(size_t)NE * XDIM * XDIM];      // tf32-rounded weights
__device__ __align__(16) float g_part[4ull * B_ROWS * XDIM];           // ksplit partials (16 MB)

__device__ __forceinline__ float eluf(float x) { return x > 0.0f ? x : expm1f(x); }
__device__ __forceinline__ float tf32r(float x) {
    float r; asm("cvt.rna.tf32.f32 %0, %1;" : "=f"(r) : "f"(x)); return r;
}

// ---------------------------------------------------------------------------
// Gating network (validated R1-R4)
// ---------------------------------------------------------------------------
__global__ __launch_bounds__(128) void gating_kernel(
    const float* __restrict__ GI,
    const float* __restrict__ Wg0, const float* __restrict__ bg0,
    const float* __restrict__ Wg1, const float* __restrict__ bg1,
    const float* __restrict__ Wgo, const float* __restrict__ bgo)
{
    __shared__ float sx[8][GIN];
    __shared__ float sh[8][GH];
    __shared__ float sl[8][NE];

    const int r0  = blockIdx.x * 8;
    const int tid = threadIdx.x;

    for (int idx = tid; idx < 8 * GIN; idx += 128)
        sx[idx >> 7][idx & 127] = GI[(size_t)(r0 + (idx >> 7)) * GIN + (idx & 127)];
    __syncthreads();

    float acc[8];
    #pragma unroll
    for (int r = 0; r < 8; r++) acc[r] = bg0[tid];
    #pragma unroll 4
    for (int i = 0; i < GIN; i++) {
        float w = Wg0[i * GH + tid];
        #pragma unroll
        for (int r = 0; r < 8; r++) acc[r] += sx[r][i] * w;
    }
    #pragma unroll
    for (int r = 0; r < 8; r++) sh[r][tid] = eluf(acc[r]);
    __syncthreads();

    #pragma unroll
    for (int r = 0; r < 8; r++) acc[r] = bg1[tid];
    #pragma unroll 4
    for (int i = 0; i < GH; i++) {
        float w = Wg1[i * GH + tid];
        #pragma unroll
        for (int r = 0; r < 8; r++) acc[r] += sh[r][i] * w;
    }
    __syncthreads();
    #pragma unroll
    for (int r = 0; r < 8; r++) sx[r][tid] = eluf(acc[r]);
    __syncthreads();

    if (tid < 64) {
        const int r = tid >> 3, e = tid & 7;
        float a = bgo[e];
        #pragma unroll 4
        for (int i = 0; i < GH; i++) a += sx[r][i] * Wgo[i * NE + e];
        sl[r][e] = a;
    }
    __syncthreads();

    if (tid < 8) {
        const int r = tid;
        float mx = sl[r][0];
        #pragma unroll
        for (int e = 1; e < NE; e++) mx = fmaxf(mx, sl[r][e]);
        float ex[NE], s = 0.0f;
        #pragma unroll
        for (int e = 0; e < NE; e++) { ex[e] = expf(sl[r][e] - mx); s += ex[e]; }
        float inv = 1.0f / s;
        #pragma unroll
        for (int e = 0; e < NE; e++)
            g_gate[(size_t)(r0 + r) * NE + e] = ex[e] * inv;
    }
}

// tf32-round a buffer (float4 grid-stride)
__global__ __launch_bounds__(256) void cvt_round_kernel(
    const float* __restrict__ src, float* __restrict__ dst, int n4)
{
    for (int i = blockIdx.x * 256 + threadIdx.x; i < n4; i += gridDim.x * 256) {
        float4 v = ((const float4*)src)[i];
        v.x = tf32r(v.x); v.y = tf32r(v.y); v.z = tf32r(v.z); v.w = tf32r(v.w);
        ((float4*)dst)[i] = v;
    }
}

// ---------------------------------------------------------------------------
// GEMM: per (n-block, m-block, ksplit) CTA covers 2 experts, single acc set
// with exact gate-ratio rescale at the expert boundary.
// Tile 128x128, 4 warps, warptile 64x64, BK=32, NST=2 cp.async.
// Fragments loaded via ldmatrix.x4 (tf32-as-2xb16 trick), PAD=36 rows.
// ---------------------------------------------------------------------------
#define BM 128
#define BN 128
#define BK 32
#define NKT 32                       // 2 experts * 512 / 32
#define PAD 36
#define STG_F (BM * PAD + BN * PAD)  // 9216 floats per stage
#define NST 2
#define SMEM_FLOATS (NST * STG_F + BM * 2 + 2 * BN)
#define SMEM_BYTES  (SMEM_FLOATS * 4)   // 75776

__device__ __forceinline__ void cp16(uint32_t dst, const float* src) {
    asm volatile("cp.async.cg.shared.global [%0], [%1], 16;"
                 :: "r"(dst), "l"(__cvta_generic_to_global(src)) : "memory");
}
__device__ __forceinline__ void ldmx4(uint32_t* r, uint32_t addr) {
    asm volatile("ldmatrix.sync.aligned.m8n8.x4.shared.b16 {%0,%1,%2,%3}, [%4];"
                 : "=r"(r[0]), "=r"(r[1]), "=r"(r[2]), "=r"(r[3]) : "r"(addr));
}
__device__ __forceinline__ void mma8(float* c, const uint32_t* a, const uint32_t* b) {
    asm volatile(
        "mma.sync.aligned.m16n8k8.row.col.f32.tf32.tf32.f32 "
        "{%0,%1,%2,%3}, {%4,%5,%6,%7}, {%8,%9}, {%0,%1,%2,%3};"
        : "+f"(c[0]), "+f"(c[1]), "+f"(c[2]), "+f"(c[3])
        : "r"(a[0]), "r"(a[1]), "r"(a[2]), "r"(a[3]), "r"(b[0]), "r"(b[1]));
}

__global__ __launch_bounds__(128) void gemm_kernel(const float* __restrict__ beta)
{
    extern __shared__ float smem[];
    float* sg    = smem + NST * STG_F;   // [128][2] gates for expert pair
    float* sbeta = sg + BM * 2;          // [2][128]

    const int tid  = threadIdx.x;
    const int wid  = tid >> 5, lane = tid & 31;
    const int qid  = lane >> 2, qk = lane & 3;
    const int wm   = (wid & 1) * 64;
    const int wn   = (wid >> 1) * 64;
    const int n0   = blockIdx.x * BN;
    const int m0   = blockIdx.y * BM;
    const int e0   = blockIdx.z * 2;

    const uint32_t smem_u = (uint32_t)__cvta_generic_to_shared(smem);

    // ldmatrix per-lane tile-row coordinates
    const int lrA = lane & 15;                       // row within 16-row tile
    const int lkA = (lane >> 4) << 2;                // k-word 0 or 4
    const int lrB = ((lane >> 4) << 3) + (lane & 7); // row within 16-row n-tile
    const int lkB = ((lane >> 3) & 1) << 2;          // k-word 0 or 4

    auto load_chunk = [&](int s, int c) {
        const int el = c >> 4;
        const int i0 = (c & 15) * 32;
        const float* Ab = g_xt + (size_t)m0 * XDIM + i0;
        const float* Bb = g_alpha + ((size_t)(e0 + el) * XDIM + n0) * XDIM + i0;
        const uint32_t sa  = smem_u + s * (STG_F * 4);
        const uint32_t sbm = sa + BM * PAD * 4;
        #pragma unroll
        for (int i = 0; i < 8; i++) {
            int unit = i * 128 + tid;
            int row = unit >> 3, c16 = unit & 7;
            cp16(sa + row * (PAD * 4) + c16 * 16, Ab + (size_t)row * XDIM + c16 * 4);
        }
        #pragma unroll
        for (int i = 0; i < 8; i++) {
            int unit = i * 128 + tid;
            int row = unit >> 3, c16 = unit & 7;
            cp16(sbm + row * (PAD * 4) + c16 * 16, Bb + (size_t)row * XDIM + c16 * 4);
        }
    };

    load_chunk(0, 0);
    asm volatile("cp.async.commit_group;" ::: "memory");
    load_chunk(1, 1);
    asm volatile("cp.async.commit_group;" ::: "memory");

    sg[tid * 2 + 0] = g_gate[(size_t)(m0 + tid) * NE + e0];
    sg[tid * 2 + 1] = g_gate[(size_t)(m0 + tid) * NE + e0 + 1];
    sbeta[tid]       = beta[(size_t)e0 * XDIM + n0 + tid];
    sbeta[128 + tid] = beta[(size_t)(e0 + 1) * XDIM + n0 + tid];

    float c[4][8][4];
    #pragma unroll
    for (int mt = 0; mt < 4; mt++)
        #pragma unroll
        for (int nt = 0; nt < 8; nt++)
            #pragma unroll
            for (int j = 0; j < 4; j++) c[mt][nt][j] = 0.0f;

    for (int kt = 0; kt < NKT; kt++) {
        asm volatile("cp.async.wait_group 1;" ::: "memory");
        __syncthreads();

        const uint32_t As_u = smem_u + (kt & 1) * (STG_F * 4);
        const uint32_t Bs_u = As_u + BM * PAD * 4;

        #pragma unroll
        for (int ks = 0; ks < 4; ks++) {
            uint32_t a[4][4], b[8][2];
            #pragma unroll
            for (int mt = 0; mt < 4; mt++)
                ldmx4(a[mt], As_u + ((wm + mt * 16 + lrA) * PAD + ks * 8 + lkA) * 4);
            #pragma unroll
            for (int p = 0; p < 4; p++) {
                uint32_t r[4];
                ldmx4(r, Bs_u + ((wn + p * 16 + lrB) * PAD + ks * 8 + lkB) * 4);
                b[2 * p][0] = r[0]; b[2 * p][1] = r[1];
                b[2 * p + 1][0] = r[2]; b[2 * p + 1][1] = r[3];
            }
            #pragma unroll
            for (int mt = 0; mt < 4; mt++)
                #pragma unroll
                for (int nt = 0; nt < 8; nt++)
                    mma8(c[mt][nt], a[mt], b[nt]);
        }

        if (kt == 15) {   // expert boundary: c *= g_e0/g_e1
            #pragma unroll
            for (int mt = 0; mt < 4; mt++) {
                const int r0 = wm + mt * 16 + qid, r1 = r0 + 8;
                const float t0 = sg[r0 * 2] / sg[r0 * 2 + 1];
                const float t1 = sg[r1 * 2] / sg[r1 * 2 + 1];
                #pragma unroll
                for (int nt = 0; nt < 8; nt++) {
                    c[mt][nt][0] *= t0; c[mt][nt][1] *= t0;
                    c[mt][nt][2] *= t1; c[mt][nt][3] *= t1;
                }
            }
        }

        __syncthreads();
        if (kt + 2 < NKT) load_chunk(kt & 1, kt + 2);
        asm volatile("cp.async.commit_group;" ::: "memory");
    }

    // epilogue -> partial buffer
    float* P = g_part + (size_t)blockIdx.z * B_ROWS * XDIM;
    #pragma unroll
    for (int mt = 0; mt < 4; mt++) {
        const int r0 = wm + mt * 16 + qid, r1 = r0 + 8;
        const float ga0 = sg[r0 * 2], gb0 = sg[r0 * 2 + 1];
        const float ga1 = sg[r1 * 2], gb1 = sg[r1 * 2 + 1];
        #pragma unroll
        for (int nt = 0; nt < 8; nt++) {
            const int cc = wn + nt * 8 + 2 * qk;
            const float be00 = sbeta[cc], be01 = sbeta[cc + 1];
            const float be10 = sbeta[128 + cc], be11 = sbeta[128 + cc + 1];
            float2 o0, o1;
            o0.x = gb0 * c[mt][nt][0] + ga0 * be00 + gb0 * be10;
            o0.y = gb0 * c[mt][nt][1] + ga0 * be01 + gb0 * be11;
            o1.x = gb1 * c[mt][nt][2] + ga1 * be00 + gb1 * be10;
            o1.y = gb1 * c[mt][nt][3] + ga1 * be01 + gb1 * be11;
            *(float2*)(P + (size_t)(m0 + r0) * XDIM + n0 + cc) = o0;
            *(float2*)(P + (size_t)(m0 + r1) * XDIM + n0 + cc) = o1;
        }
    }
}

// Sum 4 partials; mode 1: ELU + tf32-round -> g_xt; mode 0: raw -> dst
__global__ __launch_bounds__(256) void reduce_kernel(float* __restrict__ dst, int mode)
{
    const int n4 = B_ROWS * XDIM / 4;
    const float4* p0 = (const float4*)g_part;
    const float4* p1 = (const float4*)(g_part + (size_t)1 * B_ROWS * XDIM);
    const float4* p2 = (const float4*)(g_part + (size_t)2 * B_ROWS * XDIM);
    const float4* p3 = (const float4*)(g_part + (size_t)3 * B_ROWS * XDIM);
    float4* out = (mode == 1) ? (float4*)g_xt : (float4*)dst;
    for (int i = blockIdx.x * 256 + threadIdx.x; i < n4; i += gridDim.x * 256) {
        float4 a = p0[i], b = p1[i], c2 = p2[i], d = p3[i];
        float4 v;
        v.x = a.x + b.x + c2.x + d.x;
        v.y = a.y + b.y + c2.y + d.y;
        v.z = a.z + b.z + c2.z + d.z;
        v.w = a.w + b.w + c2.w + d.w;
        if (mode == 1) {
            v.x = tf32r(eluf(v.x)); v.y = tf32r(eluf(v.y));
            v.z = tf32r(eluf(v.z)); v.w = tf32r(eluf(v.w));
        }
        out[i] = v;
    }
}

// ---------------------------------------------------------------------------
extern "C" void kernel_launch(void* const* d_in, const int* in_sizes, int n_in,
                              void* d_out, int out_size) {
    const float* gi  = (const float*)d_in[0];
    const float* xin = (const float*)d_in[1];
    const float* Wg0 = (const float*)d_in[2];
    const float* bg0 = (const float*)d_in[3];
    const float* Wg1 = (const float*)d_in[4];
    const float* bg1 = (const float*)d_in[5];
    const float* Wgo = (const float*)d_in[6];
    const float* bgo = (const float*)d_in[7];
    const float* a0  = (const float*)d_in[8];
    const float* be0 = (const float*)d_in[9];
    const float* a1  = (const float*)d_in[10];
    const float* be1 = (const float*)d_in[11];
    const float* a2  = (const float*)d_in[12];
    const float* be2 = (const float*)d_in[13];
    float* out = (float*)d_out;

    static int init_done = 0;
    if (!init_done) {
        cudaFuncSetAttribute(gemm_kernel, cudaFuncAttributeMaxDynamicSharedMemorySize, SMEM_BYTES);
        init_done = 1;
    }

    float* d_xt; cudaGetSymbolAddress((void**)&d_xt, g_xt);
    float* d_al; cudaGetSymbolAddress((void**)&d_al, g_alpha);

    gating_kernel<<<B_ROWS / 8, 128>>>(gi, Wg0, bg0, Wg1, bg1, Wgo, bgo);
    cvt_round_kernel<<<256, 256>>>(xin, d_xt, B_ROWS * XDIM / 4);

    dim3 grid(XDIM / BN, B_ROWS / BM, 4);   // (4, 16, 4) = 256 CTAs

    // layer 0
    cvt_round_kernel<<<1024, 256>>>(a0, d_al, NE * XDIM * XDIM / 4);
    gemm_kernel<<<grid, 128, SMEM_BYTES>>>(be0);
    reduce_kernel<<<1024, 256>>>(nullptr, 1);
    // layer 1
    cvt_round_kernel<<<1024, 256>>>(a1, d_al, NE * XDIM * XDIM / 4);
    gemm_kernel<<<grid, 128, SMEM_BYTES>>>(be1);
    reduce_kernel<<<1024, 256>>>(nullptr, 1);
    // layer 2
    cvt_round_kernel<<<1024, 256>>>(a2, d_al, NE * XDIM * XDIM / 4);
    gemm_kernel<<<grid, 128, SMEM_BYTES>>>(be2);
    reduce_kernel<<<1024, 256>>>(out, 0);
}

// round 8
// speedup vs baseline: 6.1670x; 1.4564x over previous
#include <cuda_runtime.h>
#include <cuda_fp16.h>
#include <math.h>
#include <stdint.h>

#define B_ROWS 2048
#define GIN    128
#define GH     128
#define NE     8
#define XDIM   512

// Static scratch (allocation-free rule)
__device__ __align__(16) float  g_gate[B_ROWS * NE];
__device__ __align__(16) __half g_xt[(size_t)B_ROWS * XDIM];           // fp16 activations
__device__ __align__(16) __half g_alpha[(size_t)NE * XDIM * XDIM];     // fp16 weights (4 MB)
__device__ __align__(16) float  g_part[4ull * B_ROWS * XDIM];          // ksplit partials (16 MB)

__device__ __forceinline__ float eluf(float x) { return x > 0.0f ? x : expm1f(x); }

// ---------------------------------------------------------------------------
// Gating network (validated R1-R5)
// ---------------------------------------------------------------------------
__global__ __launch_bounds__(128) void gating_kernel(
    const float* __restrict__ GI,
    const float* __restrict__ Wg0, const float* __restrict__ bg0,
    const float* __restrict__ Wg1, const float* __restrict__ bg1,
    const float* __restrict__ Wgo, const float* __restrict__ bgo)
{
    __shared__ float sx[8][GIN];
    __shared__ float sh[8][GH];
    __shared__ float sl[8][NE];

    const int r0  = blockIdx.x * 8;
    const int tid = threadIdx.x;

    for (int idx = tid; idx < 8 * GIN; idx += 128)
        sx[idx >> 7][idx & 127] = GI[(size_t)(r0 + (idx >> 7)) * GIN + (idx & 127)];
    __syncthreads();

    float acc[8];
    #pragma unroll
    for (int r = 0; r < 8; r++) acc[r] = bg0[tid];
    #pragma unroll 4
    for (int i = 0; i < GIN; i++) {
        float w = Wg0[i * GH + tid];
        #pragma unroll
        for (int r = 0; r < 8; r++) acc[r] += sx[r][i] * w;
    }
    #pragma unroll
    for (int r = 0; r < 8; r++) sh[r][tid] = eluf(acc[r]);
    __syncthreads();

    #pragma unroll
    for (int r = 0; r < 8; r++) acc[r] = bg1[tid];
    #pragma unroll 4
    for (int i = 0; i < GH; i++) {
        float w = Wg1[i * GH + tid];
        #pragma unroll
        for (int r = 0; r < 8; r++) acc[r] += sh[r][i] * w;
    }
    __syncthreads();
    #pragma unroll
    for (int r = 0; r < 8; r++) sx[r][tid] = eluf(acc[r]);
    __syncthreads();

    if (tid < 64) {
        const int r = tid >> 3, e = tid & 7;
        float a = bgo[e];
        #pragma unroll 4
        for (int i = 0; i < GH; i++) a += sx[r][i] * Wgo[i * NE + e];
        sl[r][e] = a;
    }
    __syncthreads();

    if (tid < 8) {
        const int r = tid;
        float mx = sl[r][0];
        #pragma unroll
        for (int e = 1; e < NE; e++) mx = fmaxf(mx, sl[r][e]);
        float ex[NE], s = 0.0f;
        #pragma unroll
        for (int e = 0; e < NE; e++) { ex[e] = expf(sl[r][e] - mx); s += ex[e]; }
        float inv = 1.0f / s;
        #pragma unroll
        for (int e = 0; e < NE; e++)
            g_gate[(size_t)(r0 + r) * NE + e] = ex[e] * inv;
    }
}

// float -> half conversion (8 elems per thread-iter)
__global__ __launch_bounds__(256) void cvt_half_kernel(
    const float* __restrict__ src, __half* __restrict__ dst, int n8)
{
    for (int i = blockIdx.x * 256 + threadIdx.x; i < n8; i += gridDim.x * 256) {
        float4 v0 = ((const float4*)src)[2 * i];
        float4 v1 = ((const float4*)src)[2 * i + 1];
        __half2 h[4];
        h[0] = __floats2half2_rn(v0.x, v0.y);
        h[1] = __floats2half2_rn(v0.z, v0.w);
        h[2] = __floats2half2_rn(v1.x, v1.y);
        h[3] = __floats2half2_rn(v1.z, v1.w);
        ((uint4*)dst)[i] = *(uint4*)h;
    }
}

// ---------------------------------------------------------------------------
// fp16 GEMM: per (n-block, m-block, ksplit) CTA covers 2 experts, single acc
// set with exact gate-ratio rescale at the expert boundary.
// Tile 128x128, 4 warps, warptile 64x64, BK=64 halves, NST=2 cp.async.
// ldmatrix.x4 b16 fragments, mma.m16n8k16.f32.f16.f16.f32.
// ---------------------------------------------------------------------------
#define BM 128
#define BN 128
#define BKH 64                        // k halves per chunk
#define NKT 16                        // 2 experts * 512 / 64
#define PADH 72                       // half stride per row (144 B)
#define STG_H ((BM + BN) * PADH)      // halves per stage = 18432
#define NST 2
#define SMEM_BYTES (NST * STG_H * 2 + (BM * 2 + 2 * BN) * 4)   // 75264

__device__ __forceinline__ void cp16(uint32_t dst, const void* src) {
    asm volatile("cp.async.cg.shared.global [%0], [%1], 16;"
                 :: "r"(dst), "l"(__cvta_generic_to_global(src)) : "memory");
}
__device__ __forceinline__ void ldmx4(uint32_t* r, uint32_t addr) {
    asm volatile("ldmatrix.sync.aligned.m8n8.x4.shared.b16 {%0,%1,%2,%3}, [%4];"
                 : "=r"(r[0]), "=r"(r[1]), "=r"(r[2]), "=r"(r[3]) : "r"(addr));
}
__device__ __forceinline__ void mma16(float* c, const uint32_t* a, const uint32_t* b) {
    asm volatile(
        "mma.sync.aligned.m16n8k16.row.col.f32.f16.f16.f32 "
        "{%0,%1,%2,%3}, {%4,%5,%6,%7}, {%8,%9}, {%0,%1,%2,%3};"
        : "+f"(c[0]), "+f"(c[1]), "+f"(c[2]), "+f"(c[3])
        : "r"(a[0]), "r"(a[1]), "r"(a[2]), "r"(a[3]), "r"(b[0]), "r"(b[1]));
}

__global__ __launch_bounds__(128) void gemm_kernel(const float* __restrict__ beta)
{
    extern __shared__ __half smem[];
    float* sg    = (float*)(smem + NST * STG_H);   // [128][2]
    float* sbeta = sg + BM * 2;                    // [2][128]

    const int tid  = threadIdx.x;
    const int wid  = tid >> 5, lane = tid & 31;
    const int qid  = lane >> 2, qk = lane & 3;
    const int wm   = (wid & 1) * 64;
    const int wn   = (wid >> 1) * 64;
    const int n0   = blockIdx.x * BN;
    const int m0   = blockIdx.y * BM;
    const int e0   = blockIdx.z * 2;

    const uint32_t smem_u = (uint32_t)__cvta_generic_to_shared(smem);

    // ldmatrix lane addressing: row = lane&15, +16B for upper half of lanes
    const int lr   = lane & 15;
    const int lkB8 = (lane >> 4) * 8;   // half offset for k 8..15

    auto load_chunk = [&](int s, int c) {
        const int el = c >> 3;                 // expert within pair
        const int i0 = (c & 7) * BKH;
        const __half* Ab = g_xt + (size_t)m0 * XDIM + i0;
        const __half* Bb = g_alpha + ((size_t)(e0 + el) * XDIM + n0) * XDIM + i0;
        const uint32_t sa  = smem_u + s * (STG_H * 2);
        const uint32_t sbm = sa + BM * PADH * 2;
        #pragma unroll
        for (int i = 0; i < 8; i++) {          // A: 128 rows x 8 x16B
            int unit = i * 128 + tid;
            int row = unit >> 3, c16 = unit & 7;
            cp16(sa + row * (PADH * 2) + c16 * 16, Ab + (size_t)row * XDIM + c16 * 8);
        }
        #pragma unroll
        for (int i = 0; i < 8; i++) {          // B: 128 rows x 8 x16B
            int unit = i * 128 + tid;
            int row = unit >> 3, c16 = unit & 7;
            cp16(sbm + row * (PADH * 2) + c16 * 16, Bb + (size_t)row * XDIM + c16 * 8);
        }
    };

    load_chunk(0, 0);
    asm volatile("cp.async.commit_group;" ::: "memory");
    load_chunk(1, 1);
    asm volatile("cp.async.commit_group;" ::: "memory");

    sg[tid * 2 + 0] = g_gate[(size_t)(m0 + tid) * NE + e0];
    sg[tid * 2 + 1] = g_gate[(size_t)(m0 + tid) * NE + e0 + 1];
    sbeta[tid]       = beta[(size_t)e0 * XDIM + n0 + tid];
    sbeta[128 + tid] = beta[(size_t)(e0 + 1) * XDIM + n0 + tid];

    float c[4][8][4];
    #pragma unroll
    for (int mt = 0; mt < 4; mt++)
        #pragma unroll
        for (int nt = 0; nt < 8; nt++)
            #pragma unroll
            for (int j = 0; j < 4; j++) c[mt][nt][j] = 0.0f;

    for (int kt = 0; kt < NKT; kt++) {
        asm volatile("cp.async.wait_group 1;" ::: "memory");
        __syncthreads();

        const uint32_t As_u = smem_u + (kt & 1) * (STG_H * 2);
        const uint32_t Bs_u = As_u + BM * PADH * 2;

        #pragma unroll
        for (int ks = 0; ks < 4; ks++) {       // 4 k-steps of 16 halves
            uint32_t a[4][4], b[8][2];
            #pragma unroll
            for (int mt = 0; mt < 4; mt++)
                ldmx4(a[mt], As_u + ((wm + mt * 16 + lr) * PADH + ks * 16 + lkB8) * 2);
            #pragma unroll
            for (int p = 0; p < 4; p++) {
                uint32_t r[4];
                ldmx4(r, Bs_u + ((wn + p * 16 + lr) * PADH + ks * 16 + lkB8) * 2);
                b[2 * p][0]     = r[0]; b[2 * p + 1][0] = r[1];
                b[2 * p][1]     = r[2]; b[2 * p + 1][1] = r[3];
            }
            #pragma unroll
            for (int mt = 0; mt < 4; mt++)
                #pragma unroll
                for (int nt = 0; nt < 8; nt++)
                    mma16(c[mt][nt], a[mt], b[nt]);
        }

        if (kt == 7) {   // expert boundary: c *= g_e0/g_e1
            #pragma unroll
            for (int mt = 0; mt < 4; mt++) {
                const int r0 = wm + mt * 16 + qid, r1 = r0 + 8;
                const float t0 = sg[r0 * 2] / sg[r0 * 2 + 1];
                const float t1 = sg[r1 * 2] / sg[r1 * 2 + 1];
                #pragma unroll
                for (int nt = 0; nt < 8; nt++) {
                    c[mt][nt][0] *= t0; c[mt][nt][1] *= t0;
                    c[mt][nt][2] *= t1; c[mt][nt][3] *= t1;
                }
            }
        }

        __syncthreads();
        if (kt + 2 < NKT) load_chunk(kt & 1, kt + 2);
        asm volatile("cp.async.commit_group;" ::: "memory");
    }

    // epilogue -> partial buffer
    float* P = g_part + (size_t)blockIdx.z * B_ROWS * XDIM;
    #pragma unroll
    for (int mt = 0; mt < 4; mt++) {
        const int r0 = wm + mt * 16 + qid, r1 = r0 + 8;
        const float ga0 = sg[r0 * 2], gb0 = sg[r0 * 2 + 1];
        const float ga1 = sg[r1 * 2], gb1 = sg[r1 * 2 + 1];
        #pragma unroll
        for (int nt = 0; nt < 8; nt++) {
            const int cc = wn + nt * 8 + 2 * qk;
            const float be00 = sbeta[cc], be01 = sbeta[cc + 1];
            const float be10 = sbeta[128 + cc], be11 = sbeta[128 + cc + 1];
            float2 o0, o1;
            o0.x = gb0 * c[mt][nt][0] + ga0 * be00 + gb0 * be10;
            o0.y = gb0 * c[mt][nt][1] + ga0 * be01 + gb0 * be11;
            o1.x = gb1 * c[mt][nt][2] + ga1 * be00 + gb1 * be10;
            o1.y = gb1 * c[mt][nt][3] + ga1 * be01 + gb1 * be11;
            *(float2*)(P + (size_t)(m0 + r0) * XDIM + n0 + cc) = o0;
            *(float2*)(P + (size_t)(m0 + r1) * XDIM + n0 + cc) = o1;
        }
    }
}

// Sum 4 partials; mode 1: ELU -> half -> g_xt; mode 0: raw fp32 -> dst
__global__ __launch_bounds__(256) void reduce_kernel(float* __restrict__ dst, int mode)
{
    const int n4 = B_ROWS * XDIM / 4;
    const float4* p0 = (const float4*)g_part;
    const float4* p1 = (const float4*)(g_part + (size_t)1 * B_ROWS * XDIM);
    const float4* p2 = (const float4*)(g_part + (size_t)2 * B_ROWS * XDIM);
    const float4* p3 = (const float4*)(g_part + (size_t)3 * B_ROWS * XDIM);
    for (int i = blockIdx.x * 256 + threadIdx.x; i < n4; i += gridDim.x * 256) {
        float4 a = p0[i], b = p1[i], c2 = p2[i], d = p3[i];
        float4 v;
        v.x = a.x + b.x + c2.x + d.x;
        v.y = a.y + b.y + c2.y + d.y;
        v.z = a.z + b.z + c2.z + d.z;
        v.w = a.w + b.w + c2.w + d.w;
        if (mode == 1) {
            __half2 h[2];
            h[0] = __floats2half2_rn(eluf(v.x), eluf(v.y));
            h[1] = __floats2half2_rn(eluf(v.z), eluf(v.w));
            ((uint2*)g_xt)[i] = *(uint2*)h;
        } else {
            ((float4*)dst)[i] = v;
        }
    }
}

// ---------------------------------------------------------------------------
extern "C" void kernel_launch(void* const* d_in, const int* in_sizes, int n_in,
                              void* d_out, int out_size) {
    const float* gi  = (const float*)d_in[0];
    const float* xin = (const float*)d_in[1];
    const float* Wg0 = (const float*)d_in[2];
    const float* bg0 = (const float*)d_in[3];
    const float* Wg1 = (const float*)d_in[4];
    const float* bg1 = (const float*)d_in[5];
    const float* Wgo = (const float*)d_in[6];
    const float* bgo = (const float*)d_in[7];
    const float* a0  = (const float*)d_in[8];
    const float* be0 = (const float*)d_in[9];
    const float* a1  = (const float*)d_in[10];
    const float* be1 = (const float*)d_in[11];
    const float* a2  = (const float*)d_in[12];
    const float* be2 = (const float*)d_in[13];
    float* out = (float*)d_out;

    static int init_done = 0;
    if (!init_done) {
        cudaFuncSetAttribute(gemm_kernel, cudaFuncAttributeMaxDynamicSharedMemorySize, SMEM_BYTES);
        init_done = 1;
    }

    __half* d_xt; cudaGetSymbolAddress((void**)&d_xt, g_xt);
    __half* d_al; cudaGetSymbolAddress((void**)&d_al, g_alpha);

    gating_kernel<<<B_ROWS / 8, 128>>>(gi, Wg0, bg0, Wg1, bg1, Wgo, bgo);
    cvt_half_kernel<<<256, 256>>>(xin, d_xt, B_ROWS * XDIM / 8);

    dim3 grid(XDIM / BN, B_ROWS / BM, 4);   // (4, 16, 4) = 256 CTAs

    // layer 0
    cvt_half_kernel<<<1024, 256>>>(a0, d_al, NE * XDIM * XDIM / 8);
    gemm_kernel<<<grid, 128, SMEM_BYTES>>>(be0);
    reduce_kernel<<<1024, 256>>>(nullptr, 1);
    // layer 1
    cvt_half_kernel<<<1024, 256>>>(a1, d_al, NE * XDIM * XDIM / 8);
    gemm_kernel<<<grid, 128, SMEM_BYTES>>>(be1);
    reduce_kernel<<<1024, 256>>>(nullptr, 1);
    // layer 2
    cvt_half_kernel<<<1024, 256>>>(a2, d_al, NE * XDIM * XDIM / 8);
    gemm_kernel<<<grid, 128, SMEM_BYTES>>>(be2);
    reduce_kernel<<<1024, 256>>>(out, 0);
}